// round 10
// baseline (speedup 1.0000x reference)
#include <cuda_runtime.h>
#include <cuda_bf16.h>
#include <cstdint>

// ---------------------------------------------------------------------------
// SymbolicFeatureExtractor: per-row (seq_len, unique_count) -> 3 feats -> MLP.
// MLP output depends only on (seq_len, uniq) in [0,128]^2 -> 129x129x32 LUT
// (2.1 MB, L2-resident; inputs/outputs use streaming hints to protect it).
//
// R10: TWO rows per warp processed in ONE joint scatter pass.
// pack = (v<<8) | (row<<7) | pos  (v<32768, pos<128, row in {0,1}).
// x = slot ^ pack; x < 128 <=> same value AND same row won the slot
// (cohort of that row resolved; x==0 member is the unique winner, +1).
// Cross-row same-value collisions (E ~ 0.13/warp) stay pending and are
// retired by round 1 or the tail broadcast loop.
//
// Round 0: direct-mapped idx = v & 511 (both rows together, 8 STS + 8 LDS).
// Round 1: multiplicative hash on survivors (~16/warp).
// Tail: ballot-elect broadcast of (value,row) pairs; exact, ~0 iters typical.
//
// No intermediate syncwarp between round-0 reads and round-1 writes (R8
// analysis, unchanged by the row bit): a late round-0 reader observing a
// round-1 pack either sees a different value/row (stays pending, handled
// later) or its own value+row with a DIFFERENT pos (resolves with x!=0, no
// count; the cohort is still counted exactly once by the round-1 winner or
// the tail). The syncwarp after round-1 writes IS required.
// No clears ever: every read in a round is preceded (same round, post-sync
// or same-thread program order) by that token's own write to that slot.
// ---------------------------------------------------------------------------

#define MAX_LEN 128
#define LUT_DIM 129

__device__ float g_lut[LUT_DIM * LUT_DIM * 32];

#define LUT_PAIRS_PER_WARP 8

__global__ __launch_bounds__(256)
void build_lut_kernel(const float* __restrict__ W1, const float* __restrict__ b1,
                      const float* __restrict__ W2, const float* __restrict__ b2) {
    int warp_in_block = threadIdx.x >> 5;
    int lane = threadIdx.x & 31;
    int base = (blockIdx.x * (blockDim.x >> 5) + warp_in_block) * LUT_PAIRS_PER_WARP;
    if (base >= LUT_DIM * LUT_DIM) return;

    float w10 = W1[0 * 32 + lane];
    float w11 = W1[1 * 32 + lane];
    float w12 = W1[2 * 32 + lane];
    float bb1 = b1[lane];
    float bb2 = b2[lane];
    float w2c[32];
    #pragma unroll
    for (int k = 0; k < 32; k++) w2c[k] = W2[k * 32 + lane];

    #pragma unroll
    for (int p = 0; p < LUT_PAIRS_PER_WARP; p++) {
        int idx = base + p;
        if (idx >= LUT_DIM * LUT_DIM) break;
        int s = idx / LUT_DIM;
        int u = idx % LUT_DIM;

        float f0 = (float)s * (1.0f / MAX_LEN);
        float f1 = (float)u * (1.0f / MAX_LEN);
        float f2 = (s > 0) ? ((float)u / (float)s) : 0.0f;

        float h = bb1;
        h = fmaf(f0, w10, h);
        h = fmaf(f1, w11, h);
        h = fmaf(f2, w12, h);
        h = fmaxf(h, 0.0f);

        float o = bb2;
        #pragma unroll
        for (int k = 0; k < 32; k++) {
            float hk = __shfl_sync(0xffffffffu, h, k);
            o = fmaf(hk, w2c[k], o);
        }
        g_lut[(size_t)idx * 32 + lane] = fmaxf(o, 0.0f);
    }
}

#define WARPS_PER_BLOCK 8
#define ROWS_PER_WARP 2
#define HASH_SLOTS 512      // 16 KB/block

__global__ __launch_bounds__(WARPS_PER_BLOCK * 32, 6)
void feat_kernel(const int* __restrict__ ids, const int* __restrict__ mask,
                 float* __restrict__ out, int B) {
    __shared__ int table[WARPS_PER_BLOCK][HASH_SLOTS];

    int w    = threadIdx.x >> 5;
    int lane = threadIdx.x & 31;
    int row0 = (blockIdx.x * WARPS_PER_BLOCK + w) * ROWS_PER_WARP;
    if (row0 >= B) return;
    int row1 = row0 + 1;          // B is a multiple of ROWS_PER_WARP*WARPS
    bool has1 = row1 < B;

    int* tab = table[w];
    int lane4 = lane * 4;

    // Front-batch all 4 input loads (streaming: keep LUT resident in L2).
    const int4* id0 = (const int4*)(ids  + (size_t)row0 * MAX_LEN);
    const int4* mk0 = (const int4*)(mask + (size_t)row0 * MAX_LEN);
    const int4* id1 = (const int4*)(ids  + (size_t)row1 * MAX_LEN);
    const int4* mk1 = (const int4*)(mask + (size_t)row1 * MAX_LEN);
    int4 iv0 = __ldcs(id0 + lane);
    int4 mv0 = __ldcs(mk0 + lane);
    int4 iv1, mv1;
    if (has1) { iv1 = __ldcs(id1 + lane); mv1 = __ldcs(mk1 + lane); }
    else      { iv1 = make_int4(0,0,0,0); mv1 = make_int4(0,0,0,0); }

    int seq0 = mv0.x + mv0.y + mv0.z + mv0.w;
    int seq1 = mv1.x + mv1.y + mv1.z + mv1.w;

    int vals0[4] = {iv0.x, iv0.y, iv0.z, iv0.w};
    int vals1[4] = {iv1.x, iv1.y, iv1.z, iv1.w};
    bool pend0[4] = {mv0.x != 0, mv0.y != 0, mv0.z != 0, mv0.w != 0};
    bool pend1[4] = {mv1.x != 0, mv1.y != 0, mv1.z != 0, mv1.w != 0};

    int cnt0 = 0, cnt1 = 0;

    // ---- joint round 0: direct-mapped scatter, both rows, 8 STS ----
    #pragma unroll
    for (int t = 0; t < 4; t++) {
        if (pend0[t]) tab[(unsigned)vals0[t] & (HASH_SLOTS - 1)]
                          = vals0[t] * 256 + (lane4 + t);
        if (pend1[t]) tab[(unsigned)vals1[t] & (HASH_SLOTS - 1)]
                          = vals1[t] * 256 + 128 + (lane4 + t);
    }
    __syncwarp();
    #pragma unroll
    for (int t = 0; t < 4; t++) {
        if (pend0[t]) {
            int x = tab[(unsigned)vals0[t] & (HASH_SLOTS - 1)]
                    ^ (vals0[t] * 256 + (lane4 + t));
            if ((unsigned)x < 128u) { pend0[t] = false; cnt0 += (x == 0); }
        }
        if (pend1[t]) {
            int x = tab[(unsigned)vals1[t] & (HASH_SLOTS - 1)]
                    ^ (vals1[t] * 256 + 128 + (lane4 + t));
            if ((unsigned)x < 128u) { pend1[t] = false; cnt1 += (x == 0); }
        }
    }
    // (no syncwarp here -- safe per header analysis)

    // ---- joint round 1: multiplicative hash, survivors only (~16/warp) ----
    #pragma unroll
    for (int t = 0; t < 4; t++) {
        if (pend0[t]) tab[((unsigned)vals0[t] * 2654435761u) >> 23]
                          = vals0[t] * 256 + (lane4 + t);
        if (pend1[t]) tab[((unsigned)vals1[t] * 2654435761u) >> 23]
                          = vals1[t] * 256 + 128 + (lane4 + t);
    }
    __syncwarp();   // REQUIRED: all round-1 writes before round-1 reads
    #pragma unroll
    for (int t = 0; t < 4; t++) {
        if (pend0[t]) {
            int x = tab[((unsigned)vals0[t] * 2654435761u) >> 23]
                    ^ (vals0[t] * 256 + (lane4 + t));
            if ((unsigned)x < 128u) { pend0[t] = false; cnt0 += (x == 0); }
        }
        if (pend1[t]) {
            int x = tab[((unsigned)vals1[t] * 2654435761u) >> 23]
                    ^ (vals1[t] * 256 + 128 + (lane4 + t));
            if ((unsigned)x < 128u) { pend1[t] = false; cnt1 += (x == 0); }
        }
    }

    // ---- tail: smem-free cohort broadcast of (value,row) pairs ----
    while (true) {
        bool any = pend0[0] | pend0[1] | pend0[2] | pend0[3]
                 | pend1[0] | pend1[1] | pend1[2] | pend1[3];
        unsigned m = __ballot_sync(0xffffffffu, any);
        if (!m) break;
        int leader = __ffs(m) - 1;
        int myp = pend0[0] ? vals0[0] * 2     : pend0[1] ? vals0[1] * 2
                : pend0[2] ? vals0[2] * 2     : pend0[3] ? vals0[3] * 2
                : pend1[0] ? vals1[0] * 2 + 1 : pend1[1] ? vals1[1] * 2 + 1
                : pend1[2] ? vals1[2] * 2 + 1 : vals1[3] * 2 + 1;
        int lp = __shfl_sync(0xffffffffu, myp, leader);
        int lv = lp >> 1;
        if (lane == leader) { if (lp & 1) cnt1++; else cnt0++; }
        if (lp & 1) {
            #pragma unroll
            for (int t = 0; t < 4; t++) pend1[t] &= (vals1[t] != lv);
        } else {
            #pragma unroll
            for (int t = 0; t < 4; t++) pend0[t] &= (vals0[t] != lv);
        }
    }

    // LUT index is linear in per-lane partials: one REDUX per row.
    int idx0 = __reduce_add_sync(0xffffffffu, seq0 * LUT_DIM + cnt0);
    int idx1 = __reduce_add_sync(0xffffffffu, seq1 * LUT_DIM + cnt1);

    float v0 = g_lut[(size_t)idx0 * 32 + lane];
    float v1 = g_lut[(size_t)idx1 * 32 + lane];
    __stcs(&out[(size_t)row0 * 32 + lane], v0);
    if (has1) __stcs(&out[(size_t)row1 * 32 + lane], v1);
}

extern "C" void kernel_launch(void* const* d_in, const int* in_sizes, int n_in,
                              void* d_out, int out_size) {
    const int*   ids  = (const int*)d_in[0];
    const int*   mask = (const int*)d_in[1];
    const float* W1   = (const float*)d_in[2];
    const float* b1   = (const float*)d_in[3];
    const float* W2   = (const float*)d_in[4];
    const float* b2   = (const float*)d_in[5];
    float* out = (float*)d_out;

    int B = in_sizes[0] / MAX_LEN;

    int lut_pairs  = LUT_DIM * LUT_DIM;
    int pairs_per_block = 8 * LUT_PAIRS_PER_WARP;
    int lut_blocks = (lut_pairs + pairs_per_block - 1) / pairs_per_block;
    build_lut_kernel<<<lut_blocks, 256>>>(W1, b1, W2, b2);

    int rows_per_block = WARPS_PER_BLOCK * ROWS_PER_WARP;
    int blocks = (B + rows_per_block - 1) / rows_per_block;
    feat_kernel<<<blocks, WARPS_PER_BLOCK * 32>>>(ids, mask, out, B);
}

// round 11
// speedup vs baseline: 1.1920x; 1.1920x over previous
#include <cuda_runtime.h>
#include <cuda_bf16.h>
#include <cstdint>

// ---------------------------------------------------------------------------
// SymbolicFeatureExtractor: per-row (seq_len, unique_count) -> 3 feats -> MLP.
// MLP output depends only on (seq_len, uniq) in [0,128]^2 -> 129x129x32 LUT
// (2.1 MB, L2-resident; inputs/outputs use streaming hints to protect it).
//
// R11 = R9 (two rows per warp, sequential passes through one 512-slot table)
// with reduced synchronization:
//   * 2 syncwarps per row (after each round's WRITES) instead of 3.
//   * No sync between a round's reads and the next round's writes: a late
//     reader observing a newer pack either sees a different value/row
//     (stays pending -> handled by the next round or the exact tail loop)
//     or its own value with a different pos (resolves WITHOUT counting; the
//     cohort is still counted exactly once downstream). Row isolation is
//     guaranteed by the tail loop's unconditional __ballot_sync (warp
//     convergence; every lane's ballot input data-depends on its completed
//     reads), plus a row bit in the pack as defense-in-depth.
// pack = v*256 + row*128 + pos; x = slot^pack; x<128 <=> same value+row won
// (cohort resolved; the x==0 member is the unique winner, counts 1).
// No clears ever: every read is preceded by that token's own same-round
// write to the same slot.
// ---------------------------------------------------------------------------

#define MAX_LEN 128
#define LUT_DIM 129

__device__ float g_lut[LUT_DIM * LUT_DIM * 32];

#define LUT_PAIRS_PER_WARP 8

__global__ __launch_bounds__(256)
void build_lut_kernel(const float* __restrict__ W1, const float* __restrict__ b1,
                      const float* __restrict__ W2, const float* __restrict__ b2) {
    int warp_in_block = threadIdx.x >> 5;
    int lane = threadIdx.x & 31;
    int base = (blockIdx.x * (blockDim.x >> 5) + warp_in_block) * LUT_PAIRS_PER_WARP;
    if (base >= LUT_DIM * LUT_DIM) return;

    float w10 = W1[0 * 32 + lane];
    float w11 = W1[1 * 32 + lane];
    float w12 = W1[2 * 32 + lane];
    float bb1 = b1[lane];
    float bb2 = b2[lane];
    float w2c[32];
    #pragma unroll
    for (int k = 0; k < 32; k++) w2c[k] = W2[k * 32 + lane];

    #pragma unroll
    for (int p = 0; p < LUT_PAIRS_PER_WARP; p++) {
        int idx = base + p;
        if (idx >= LUT_DIM * LUT_DIM) break;
        int s = idx / LUT_DIM;
        int u = idx % LUT_DIM;

        float f0 = (float)s * (1.0f / MAX_LEN);
        float f1 = (float)u * (1.0f / MAX_LEN);
        float f2 = (s > 0) ? ((float)u / (float)s) : 0.0f;

        float h = bb1;
        h = fmaf(f0, w10, h);
        h = fmaf(f1, w11, h);
        h = fmaf(f2, w12, h);
        h = fmaxf(h, 0.0f);

        float o = bb2;
        #pragma unroll
        for (int k = 0; k < 32; k++) {
            float hk = __shfl_sync(0xffffffffu, h, k);
            o = fmaf(hk, w2c[k], o);
        }
        g_lut[(size_t)idx * 32 + lane] = fmaxf(o, 0.0f);
    }
}

#define WARPS_PER_BLOCK 8
#define ROWS_PER_WARP 2
#define HASH_SLOTS 512      // 16 KB/block

// Count uniques for one row's 4 tokens. row_tag is 0 or 128 (row bit).
__device__ __forceinline__ int count_uniques(int* tab, const int4& iv,
                                             const int4& mv, int lane,
                                             int row_tag) {
    int vals[4] = {iv.x, iv.y, iv.z, iv.w};
    bool pend[4] = {mv.x != 0, mv.y != 0, mv.z != 0, mv.w != 0};

    int base_pos = row_tag + lane * 4;
    int pack[4];
    #pragma unroll
    for (int t = 0; t < 4; t++)
        pack[t] = vals[t] * 256 + (base_pos + t);   // (v<<8)|(row<<7)|pos

    int cnt = 0;
    unsigned h[4];

    // round 0: direct-mapped
    #pragma unroll
    for (int t = 0; t < 4; t++) {
        h[t] = (unsigned)vals[t] & (HASH_SLOTS - 1);
        if (pend[t]) tab[h[t]] = pack[t];
    }
    __syncwarp();                      // writes before reads (required)
    #pragma unroll
    for (int t = 0; t < 4; t++) {
        if (pend[t]) {
            int x = tab[h[t]] ^ pack[t];
            if ((unsigned)x < 128u) { pend[t] = false; cnt += (x == 0); }
        }
    }
    // no syncwarp: benign-misread analysis (header)

    // round 1: multiplicative hash, survivors only
    #pragma unroll
    for (int t = 0; t < 4; t++) {
        if (pend[t]) {
            h[t] = ((unsigned)vals[t] * 2654435761u) >> 23;
            tab[h[t]] = pack[t];
        }
    }
    __syncwarp();                      // writes before reads (required)
    #pragma unroll
    for (int t = 0; t < 4; t++) {
        if (pend[t]) {
            int x = tab[h[t]] ^ pack[t];
            if ((unsigned)x < 128u) { pend[t] = false; cnt += (x == 0); }
        }
    }
    // no syncwarp: tail ballot converges the warp; ballot input depends on
    // completed reads, so no lane can proceed to later writes early.

    // tail: smem-free cohort broadcast (exact; ~0 iterations typical)
    while (true) {
        bool any = pend[0] | pend[1] | pend[2] | pend[3];
        unsigned m = __ballot_sync(0xffffffffu, any);
        if (!m) break;
        int leader = __ffs(m) - 1;
        int myv = pend[0] ? vals[0] : pend[1] ? vals[1]
                : pend[2] ? vals[2] : vals[3];
        int lv = __shfl_sync(0xffffffffu, myv, leader);
        cnt += (lane == leader);
        #pragma unroll
        for (int t = 0; t < 4; t++)
            pend[t] &= (vals[t] != lv);
    }
    return cnt;
}

__global__ __launch_bounds__(WARPS_PER_BLOCK * 32, 6)
void feat_kernel(const int* __restrict__ ids, const int* __restrict__ mask,
                 float* __restrict__ out, int B) {
    __shared__ int table[WARPS_PER_BLOCK][HASH_SLOTS];

    int w    = threadIdx.x >> 5;
    int lane = threadIdx.x & 31;
    int row0 = (blockIdx.x * WARPS_PER_BLOCK + w) * ROWS_PER_WARP;
    if (row0 >= B) return;
    int row1 = row0 + 1;
    bool has1 = row1 < B;

    int* tab = table[w];

    // Front-batch all 4 input loads (MLP 4, streaming to protect L2 LUT).
    const int4* id0 = (const int4*)(ids  + (size_t)row0 * MAX_LEN);
    const int4* mk0 = (const int4*)(mask + (size_t)row0 * MAX_LEN);
    const int4* id1 = (const int4*)(ids  + (size_t)row1 * MAX_LEN);
    const int4* mk1 = (const int4*)(mask + (size_t)row1 * MAX_LEN);
    int4 iv0 = __ldcs(id0 + lane);
    int4 mv0 = __ldcs(mk0 + lane);
    int4 iv1, mv1;
    if (has1) { iv1 = __ldcs(id1 + lane); mv1 = __ldcs(mk1 + lane); }
    else      { iv1 = make_int4(0,0,0,0); mv1 = make_int4(0,0,0,0); }

    int seq0 = mv0.x + mv0.y + mv0.z + mv0.w;
    int seq1 = mv1.x + mv1.y + mv1.z + mv1.w;

    int cnt0 = count_uniques(tab, iv0, mv0, lane, 0);
    int cnt1 = count_uniques(tab, iv1, mv1, lane, 128);

    // LUT index is linear in per-lane partials: one REDUX per row.
    int idx0 = __reduce_add_sync(0xffffffffu, seq0 * LUT_DIM + cnt0);
    int idx1 = __reduce_add_sync(0xffffffffu, seq1 * LUT_DIM + cnt1);

    float v0 = g_lut[(size_t)idx0 * 32 + lane];
    float v1 = g_lut[(size_t)idx1 * 32 + lane];
    __stcs(&out[(size_t)row0 * 32 + lane], v0);
    if (has1) __stcs(&out[(size_t)row1 * 32 + lane], v1);
}

extern "C" void kernel_launch(void* const* d_in, const int* in_sizes, int n_in,
                              void* d_out, int out_size) {
    const int*   ids  = (const int*)d_in[0];
    const int*   mask = (const int*)d_in[1];
    const float* W1   = (const float*)d_in[2];
    const float* b1   = (const float*)d_in[3];
    const float* W2   = (const float*)d_in[4];
    const float* b2   = (const float*)d_in[5];
    float* out = (float*)d_out;

    int B = in_sizes[0] / MAX_LEN;

    int lut_pairs  = LUT_DIM * LUT_DIM;
    int pairs_per_block = 8 * LUT_PAIRS_PER_WARP;
    int lut_blocks = (lut_pairs + pairs_per_block - 1) / pairs_per_block;
    build_lut_kernel<<<lut_blocks, 256>>>(W1, b1, W2, b2);

    int rows_per_block = WARPS_PER_BLOCK * ROWS_PER_WARP;
    int blocks = (B + rows_per_block - 1) / rows_per_block;
    feat_kernel<<<blocks, WARPS_PER_BLOCK * 32>>>(ids, mask, out, B);
}